// round 1
// baseline (speedup 1.0000x reference)
#include <cuda_runtime.h>

#define BH   32
#define LTOT 4096
#define DD   128
#define MM   640
#define TL   64
#define TM   64
#define NMT  (MM/TM)    // 10
#define NLT  (LTOT/TL)  // 64
#define KS   132        // padded stride for 128-wide fp32 tiles
#define PS   68         // padded stride for phi^T tile (multiple of 4)

#define SMEM_FLOATS (TL*KS + TM*KS + TM*PS + TL)

// scratch: context [BH, M, D] fp32 (10.5 MB) + phi_k column sums [BH, M]
__device__ float g_ctx[(size_t)BH * MM * DD];
__device__ float g_ksum[BH * MM];

__device__ __forceinline__ void dot4(float& a, const float4& x, const float4& y) {
    a = fmaf(x.x, y.x, a);
    a = fmaf(x.y, y.y, a);
    a = fmaf(x.z, y.z, a);
    a = fmaf(x.w, y.w, a);
}

__device__ __forceinline__ void axpy8(float* dst, float s, const float4& v0, const float4& v1) {
    dst[0] = fmaf(s, v0.x, dst[0]);
    dst[1] = fmaf(s, v0.y, dst[1]);
    dst[2] = fmaf(s, v0.z, dst[2]);
    dst[3] = fmaf(s, v0.w, dst[3]);
    dst[4] = fmaf(s, v1.x, dst[4]);
    dst[5] = fmaf(s, v1.y, dst[5]);
    dst[6] = fmaf(s, v1.z, dst[6]);
    dst[7] = fmaf(s, v1.w, dst[7]);
}

// Constants:
//   inv_ssd  = 1 / 128^0.25
//   inv2sqd  = 1 / (2*sqrt(128))
//   cadd     = EPS - 0.5*ln(640)   (folds the 1/sqrt(M) into the exp)
#define INV_SSD  0.2973017787506803f
#define INV2SQD  0.04419417382415922f
#define CADD    -3.2306341575510305f

// ---------------------------------------------------------------------------
// K1: per (bh, M-tile): context[Mtile, D] = sum_l phi(k_l) outer v_l,
//     ksum[Mtile] = sum_l phi(k_l).  phi computed on the fly.
// ---------------------------------------------------------------------------
__global__ __launch_bounds__(256, 2) void k1_ctx_kernel(
    const float* __restrict__ kin, const float* __restrict__ vin,
    const float* __restrict__ proj)
{
    extern __shared__ float sm[];
    float* k_s  = sm;                 // [TL][KS]
    float* p_s  = sm + TL*KS;         // [TM][KS]
    float* phiT = p_s + TM*KS;        // [TM][PS]  phi^T: [m][l]
    float* g_s  = phiT + TM*PS;       // [TL]

    const int bh = blockIdx.x / NMT;
    const int mt = blockIdx.x % NMT;
    const int t  = threadIdx.x;
    const int tx = t & 15, ty = t >> 4;

    // load P tile (resident for whole block)
    {
        const float4* Pg = (const float4*)(proj + (size_t)(mt*TM)*DD);
        #pragma unroll
        for (int r = 0; r < 8; r++) {
            int i = t + r*256;                  // 0..2047
            int row = i >> 5, c = i & 31;
            float4 val = Pg[i];
            *(float4*)&p_s[row*KS + c*4] = val;
        }
    }

    const float* kg = kin + (size_t)bh*LTOT*DD;
    const float* vg = vin + (size_t)bh*LTOT*DD;

    float ctx[4][8];
    float ksacc[4];
    #pragma unroll
    for (int i = 0; i < 4; i++) {
        ksacc[i] = 0.f;
        #pragma unroll
        for (int j = 0; j < 8; j++) ctx[i][j] = 0.f;
    }

    for (int lc = 0; lc < NLT; lc++) {
        __syncthreads();  // prev accum done (phiT safe) — loads below touch k_s only
        {
            const float4* krow = (const float4*)(kg + (size_t)lc*TL*DD);
            #pragma unroll
            for (int r = 0; r < 8; r++) {
                int i = t + r*256;
                int row = i >> 5, c = i & 31;
                float4 val = krow[i];
                *(float4*)&k_s[row*KS + c*4] = val;
            }
        }
        __syncthreads();
        if (t < TL) {
            float s = 0.f;
            #pragma unroll 16
            for (int d = 0; d < DD; d++) { float x = k_s[t*KS + d]; s = fmaf(x, x, s); }
            g_s[t] = s * INV2SQD;
        }
        __syncthreads();

        // S = K_tile * P_tile^T  (64l x 64m), 4x4 per thread, strided by 16
        float acc[4][4];
        #pragma unroll
        for (int i = 0; i < 4; i++)
            #pragma unroll
            for (int j = 0; j < 4; j++) acc[i][j] = 0.f;

        #pragma unroll 4
        for (int kk = 0; kk < DD; kk += 4) {
            float4 kv[4], pv[4];
            #pragma unroll
            for (int j = 0; j < 4; j++) kv[j] = *(const float4*)&k_s[(ty + 16*j)*KS + kk];
            #pragma unroll
            for (int i = 0; i < 4; i++) pv[i] = *(const float4*)&p_s[(tx + 16*i)*KS + kk];
            #pragma unroll
            for (int i = 0; i < 4; i++)
                #pragma unroll
                for (int j = 0; j < 4; j++) dot4(acc[i][j], pv[i], kv[j]);
        }
        #pragma unroll
        for (int i = 0; i < 4; i++)
            #pragma unroll
            for (int j = 0; j < 4; j++) {
                int l = ty + 16*j;
                phiT[(tx + 16*i)*PS + l] = __expf(fmaf(acc[i][j], INV_SSD, CADD - g_s[l]));
            }
        __syncthreads();

        // context accumulation: thread owns m = ty*4+i (4), d = tx*8+j (8)
        const float4* vrow = (const float4*)(vg + (size_t)lc*TL*DD);
        #pragma unroll 4
        for (int l = 0; l < TL; l++) {
            float4 v0 = vrow[l*32 + tx*2];
            float4 v1 = vrow[l*32 + tx*2 + 1];
            #pragma unroll
            for (int i = 0; i < 4; i++) {
                float ph = phiT[(ty*4 + i)*PS + l];
                ksacc[i] += ph;
                axpy8(ctx[i], ph, v0, v1);
            }
        }
    }

    // write context tile + ksum
    float* cg = g_ctx + ((size_t)bh*MM + mt*TM)*DD;
    #pragma unroll
    for (int i = 0; i < 4; i++) {
        float4 o0 = make_float4(ctx[i][0], ctx[i][1], ctx[i][2], ctx[i][3]);
        float4 o1 = make_float4(ctx[i][4], ctx[i][5], ctx[i][6], ctx[i][7]);
        *(float4*)&cg[(ty*4 + i)*DD + tx*8]     = o0;
        *(float4*)&cg[(ty*4 + i)*DD + tx*8 + 4] = o1;
    }
    if (tx == 0) {
        #pragma unroll
        for (int i = 0; i < 4; i++) g_ksum[bh*MM + mt*TM + ty*4 + i] = ksacc[i];
    }
}

// ---------------------------------------------------------------------------
// K2: per (bh, L-tile): out = (phi(q) @ context) / (phi(q) @ ksum)
//     phi(q) computed on the fly, M processed in chunks of 64.
// ---------------------------------------------------------------------------
__global__ __launch_bounds__(256, 2) void k2_out_kernel(
    const float* __restrict__ qin, const float* __restrict__ proj,
    float* __restrict__ out)
{
    extern __shared__ float sm[];
    float* q_s  = sm;                 // [TL][KS]
    float* p_s  = sm + TL*KS;         // [TM][KS]
    float* phiT = p_s + TM*KS;        // [TM][PS]
    float* g_s  = phiT + TM*PS;       // [TL]

    const int bh = blockIdx.x / NLT;
    const int lt = blockIdx.x % NLT;
    const int t  = threadIdx.x;
    const int tx = t & 15, ty = t >> 4;

    // load Q tile once
    {
        const float4* qrow = (const float4*)(qin + ((size_t)bh*LTOT + lt*TL)*DD);
        #pragma unroll
        for (int r = 0; r < 8; r++) {
            int i = t + r*256;
            int row = i >> 5, c = i & 31;
            float4 val = qrow[i];
            *(float4*)&q_s[row*KS + c*4] = val;
        }
    }
    __syncthreads();
    if (t < TL) {
        float s = 0.f;
        #pragma unroll 16
        for (int d = 0; d < DD; d++) { float x = q_s[t*KS + d]; s = fmaf(x, x, s); }
        g_s[t] = s * INV2SQD;
    }

    float oacc[4][8];
    float dacc[4];
    #pragma unroll
    for (int i = 0; i < 4; i++) {
        dacc[i] = 0.f;
        #pragma unroll
        for (int j = 0; j < 8; j++) oacc[i][j] = 0.f;
    }

    for (int mc = 0; mc < NMT; mc++) {
        // load P chunk; the sync after also orders prev-accum (phiT reads) vs S writes
        {
            const float4* Pg = (const float4*)(proj + (size_t)(mc*TM)*DD);
            #pragma unroll
            for (int r = 0; r < 8; r++) {
                int i = t + r*256;
                int row = i >> 5, c = i & 31;
                float4 val = Pg[i];
                *(float4*)&p_s[row*KS + c*4] = val;
            }
        }
        __syncthreads();

        float acc[4][4];
        #pragma unroll
        for (int i = 0; i < 4; i++)
            #pragma unroll
            for (int j = 0; j < 4; j++) acc[i][j] = 0.f;

        #pragma unroll 4
        for (int kk = 0; kk < DD; kk += 4) {
            float4 qv[4], pv[4];
            #pragma unroll
            for (int j = 0; j < 4; j++) qv[j] = *(const float4*)&q_s[(ty + 16*j)*KS + kk];
            #pragma unroll
            for (int i = 0; i < 4; i++) pv[i] = *(const float4*)&p_s[(tx + 16*i)*KS + kk];
            #pragma unroll
            for (int i = 0; i < 4; i++)
                #pragma unroll
                for (int j = 0; j < 4; j++) dot4(acc[i][j], pv[i], qv[j]);
        }
        #pragma unroll
        for (int i = 0; i < 4; i++)
            #pragma unroll
            for (int j = 0; j < 4; j++) {
                int l = ty + 16*j;
                phiT[(tx + 16*i)*PS + l] = __expf(fmaf(acc[i][j], INV_SSD, CADD - g_s[l]));
            }
        __syncthreads();

        // accumulate out += phi^T-slice * context-chunk; D += phi * ksum
        const float* ctxg = g_ctx + ((size_t)bh*MM + mc*TM)*DD;
        const float* ksg  = g_ksum + bh*MM + mc*TM;
        #pragma unroll 2
        for (int m = 0; m < TM; m++) {
            float4 ph = *(const float4*)&phiT[m*PS + ty*4];   // l = ty*4..+3
            float4 c0 = __ldg((const float4*)&ctxg[m*DD + tx*8]);
            float4 c1 = __ldg((const float4*)&ctxg[m*DD + tx*8 + 4]);
            float  ks = __ldg(&ksg[m]);
            float phs[4] = {ph.x, ph.y, ph.z, ph.w};
            #pragma unroll
            for (int i = 0; i < 4; i++) {
                dacc[i] = fmaf(phs[i], ks, dacc[i]);
                axpy8(oacc[i], phs[i], c0, c1);
            }
        }
        __syncthreads();
    }

    // normalize + write: row l = lt*TL + ty*4 + i, cols tx*8..
    float* og = out + ((size_t)bh*LTOT + lt*TL)*DD;
    #pragma unroll
    for (int i = 0; i < 4; i++) {
        float inv = 1.0f / dacc[i];
        float4 o0 = make_float4(oacc[i][0]*inv, oacc[i][1]*inv, oacc[i][2]*inv, oacc[i][3]*inv);
        float4 o1 = make_float4(oacc[i][4]*inv, oacc[i][5]*inv, oacc[i][6]*inv, oacc[i][7]*inv);
        *(float4*)&og[(ty*4 + i)*DD + tx*8]     = o0;
        *(float4*)&og[(ty*4 + i)*DD + tx*8 + 4] = o1;
    }
}

extern "C" void kernel_launch(void* const* d_in, const int* in_sizes, int n_in,
                              void* d_out, int out_size) {
    const float* q    = (const float*)d_in[0];
    const float* k    = (const float*)d_in[1];
    const float* v    = (const float*)d_in[2];
    const float* proj = (const float*)d_in[3];
    float* out = (float*)d_out;

    size_t smem = SMEM_FLOATS * sizeof(float);   // 85,248 B
    cudaFuncSetAttribute(k1_ctx_kernel, cudaFuncAttributeMaxDynamicSharedMemorySize, (int)smem);
    cudaFuncSetAttribute(k2_out_kernel, cudaFuncAttributeMaxDynamicSharedMemorySize, (int)smem);

    k1_ctx_kernel<<<BH * NMT, 256, smem>>>(k, v, proj);
    k2_out_kernel<<<BH * NLT, 256, smem>>>(q, proj, out);
}

// round 5
// speedup vs baseline: 3.2563x; 3.2563x over previous
#include <cuda_runtime.h>
#include <cstdint>

#define BH   32
#define LTOT 4096
#define DD   128
#define MM   640
#define TL   64
#define TM   64
#define NMT  (MM/TM)    // 10
#define NLT  (LTOT/TL)  // 64
#define LDX  132        // padded stride for 128-wide fp32 tiles (132 mod 32 == 4)
#define PT   68         // padded stride for phi tiles (68 mod 32 == 4)

#define INV_SSD  0.2973017787506803f
#define INV2SQD  0.04419417382415922f
#define CADD    -3.2306341575510305f

// scratch: context [BH, M, D] fp32 + phi_k column sums [BH, M]
__device__ float g_ctx[(size_t)BH * MM * DD];
__device__ float g_ksum[BH * MM];

__device__ __forceinline__ float to_tf32(float x) {
    uint32_t u;
    asm("cvt.rna.tf32.f32 %0, %1;" : "=r"(u) : "f"(x));
    return __uint_as_float(u);
}

__device__ __forceinline__ void mma8(float* c, const uint32_t* a, const uint32_t* b) {
    asm volatile(
        "mma.sync.aligned.m16n8k8.row.col.f32.tf32.tf32.f32 "
        "{%0,%1,%2,%3},{%4,%5,%6,%7},{%8,%9},{%0,%1,%2,%3};\n"
        : "+f"(c[0]), "+f"(c[1]), "+f"(c[2]), "+f"(c[3])
        : "r"(a[0]), "r"(a[1]), "r"(a[2]), "r"(a[3]), "r"(b[0]), "r"(b[1]));
}

// ---------------------------------------------------------------------------
// K1: per (bh, m-tile of 64): ctx[64, 128] = phi_k^T @ V ; ksum[64] = phi_k^T 1
// ---------------------------------------------------------------------------
__global__ __launch_bounds__(256, 2) void k1_ctx_kernel(
    const float* __restrict__ kin, const float* __restrict__ vin,
    const float* __restrict__ proj)
{
    extern __shared__ float sm[];
    float* kv_s = sm;               // [64][132]  K chunk, then V chunk
    float* p_s  = kv_s + TL*LDX;    // [64][132]  P tile (persistent)
    float* phiT = p_s  + TM*LDX;    // [64 m][68 l]
    float* g_s  = phiT + TM*PT;     // [64]
    float* red  = g_s + 64;         // [256]

    const int bh = blockIdx.x / NMT;
    const int mt = blockIdx.x % NMT;
    const int t  = threadIdx.x;
    const int w  = t >> 5, lane = t & 31;
    const int gid = lane >> 2, t4 = lane & 3;

    // P tile (rows mt*64..mt*64+63), tf32-rounded
    {
        const float4* Pg = (const float4*)(proj + (size_t)(mt*TM)*DD);
        #pragma unroll
        for (int r = 0; r < 8; r++) {
            int i = t + r*256;
            float4 v = Pg[i];
            v.x = to_tf32(v.x); v.y = to_tf32(v.y); v.z = to_tf32(v.z); v.w = to_tf32(v.w);
            *(float4*)&p_s[(i>>5)*LDX + (i&31)*4] = v;
        }
    }

    const float* kg = kin + (size_t)bh*LTOT*DD;
    const float* vg = vin + (size_t)bh*LTOT*DD;

    const int lb = w & 3, mh = w >> 2;   // GEMM A warp tile: S[16l x 32m]
    const int mb = w & 3, db = w >> 2;   // GEMM B warp tile: ctx[16m x 64d]

    float ctxacc[8][4];
    #pragma unroll
    for (int nb = 0; nb < 8; nb++)
        #pragma unroll
        for (int i = 0; i < 4; i++) ctxacc[nb][i] = 0.f;
    float ksr = 0.f;
    const int km = t & 63, kq = t >> 6;

    for (int lc = 0; lc < NLT; lc++) {
        __syncthreads();   // prev GEMM B reads of kv_s/phiT complete
        // load K chunk (tf32 into smem); g in full fp32 via warp reduce:
        // thread t loads column segment (t&31), rows 8r + w -> whole warp shares a row
        {
            const float4* Kg = (const float4*)(kg + (size_t)lc*TL*DD);
            #pragma unroll
            for (int r = 0; r < 8; r++) {
                int i = t + r*256;
                float4 v = Kg[i];
                float ss = v.x*v.x + v.y*v.y + v.z*v.z + v.w*v.w;
                ss += __shfl_xor_sync(0xffffffffu, ss, 16);
                ss += __shfl_xor_sync(0xffffffffu, ss, 8);
                ss += __shfl_xor_sync(0xffffffffu, ss, 4);
                ss += __shfl_xor_sync(0xffffffffu, ss, 2);
                ss += __shfl_xor_sync(0xffffffffu, ss, 1);
                if (lane == 0) g_s[r*8 + w] = ss * INV2SQD;
                v.x = to_tf32(v.x); v.y = to_tf32(v.y); v.z = to_tf32(v.z); v.w = to_tf32(v.w);
                *(float4*)&kv_s[(i>>5)*LDX + (i&31)*4] = v;
            }
        }
        __syncthreads();

        // GEMM A: S = K_chunk @ P^T   (A = K rows l, B(k=d,n=m) = p_s[m][d])
        float c[4][4];
        #pragma unroll
        for (int nb = 0; nb < 4; nb++)
            #pragma unroll
            for (int i = 0; i < 4; i++) c[nb][i] = 0.f;
        #pragma unroll
        for (int kk = 0; kk < DD; kk += 8) {
            uint32_t a[4], b[2];
            const float* A0 = kv_s + (lb*16 + gid)*LDX + kk + t4;
            a[0] = __float_as_uint(A0[0]);
            a[1] = __float_as_uint(A0[8*LDX]);
            a[2] = __float_as_uint(A0[4]);
            a[3] = __float_as_uint(A0[8*LDX + 4]);
            #pragma unroll
            for (int nb = 0; nb < 4; nb++) {
                const float* B0 = p_s + (mh*32 + nb*8 + gid)*LDX + kk + t4;
                b[0] = __float_as_uint(B0[0]);
                b[1] = __float_as_uint(B0[4]);
                mma8(c[nb], a, b);
            }
        }
        __syncthreads();   // kv_s reads done; g_s visible everywhere

        // exp -> phiT[m][l] (tf32), then reload kv_s with V chunk
        #pragma unroll
        for (int nb = 0; nb < 4; nb++) {
            int m0 = mh*32 + nb*8 + 2*t4;
            #pragma unroll
            for (int i = 0; i < 4; i++) {
                int l = lb*16 + gid + ((i >> 1) << 3);
                float ph = __expf(fmaf(c[nb][i], INV_SSD, CADD - g_s[l]));
                phiT[(m0 + (i & 1))*PT + l] = to_tf32(ph);
            }
        }
        {
            const float4* Vg = (const float4*)(vg + (size_t)lc*TL*DD);
            #pragma unroll
            for (int r = 0; r < 8; r++) {
                int i = t + r*256;
                float4 v = Vg[i];
                v.x = to_tf32(v.x); v.y = to_tf32(v.y); v.z = to_tf32(v.z); v.w = to_tf32(v.w);
                *(float4*)&kv_s[(i>>5)*LDX + (i&31)*4] = v;
            }
        }
        __syncthreads();

        // GEMM B: ctx += phiT(16m x 64l) @ V(64l x 64d-half)
        #pragma unroll
        for (int kk = 0; kk < TL; kk += 8) {
            uint32_t a[4];
            const float* A0 = phiT + (mb*16 + gid)*PT + kk + t4;
            a[0] = __float_as_uint(A0[0]);
            a[1] = __float_as_uint(A0[8*PT]);
            a[2] = __float_as_uint(A0[4]);
            a[3] = __float_as_uint(A0[8*PT + 4]);
            #pragma unroll
            for (int nb = 0; nb < 8; nb++) {
                uint32_t b[2];
                const float* B0 = kv_s + (kk + t4)*LDX + db*64 + nb*8 + gid;
                b[0] = __float_as_uint(B0[0]);
                b[1] = __float_as_uint(B0[4*LDX]);
                mma8(ctxacc[nb], a, b);
            }
        }
        // ksum partial: m = km, l-range = kq*16..
        #pragma unroll
        for (int l0 = 0; l0 < 16; l0++)
            ksr += phiT[km*PT + kq*16 + l0];
    }

    // write ctx tile
    float* cg = g_ctx + ((size_t)bh*MM + mt*TM)*DD;
    #pragma unroll
    for (int nb = 0; nb < 8; nb++) {
        int m0 = mb*16 + gid;
        int d  = db*64 + nb*8 + 2*t4;
        *(float2*)&cg[m0*DD + d]       = make_float2(ctxacc[nb][0], ctxacc[nb][1]);
        *(float2*)&cg[(m0 + 8)*DD + d] = make_float2(ctxacc[nb][2], ctxacc[nb][3]);
    }
    red[kq*64 + km] = ksr;
    __syncthreads();
    if (t < 64)
        g_ksum[bh*MM + mt*TM + t] = red[t] + red[64 + t] + red[128 + t] + red[192 + t];
}

// ---------------------------------------------------------------------------
// K2: per (bh, l-tile of 64): out = (phi_q @ ctx) / (phi_q @ ksum)
// ---------------------------------------------------------------------------
__global__ __launch_bounds__(256, 2) void k2_out_kernel(
    const float* __restrict__ qin, const float* __restrict__ proj,
    float* __restrict__ out)
{
    extern __shared__ float sm[];
    float* q_s   = sm;               // [64][132]  Q tile (persistent)
    float* pc_s  = q_s + TL*LDX;     // [64][132]  P chunk, then ctx chunk
    float* phi_s = pc_s + TM*LDX;    // [64 l][68 m]
    float* g_s   = phi_s + TL*PT;    // [64]
    float* ks_s  = g_s + 64;         // [64]
    float* red   = ks_s + 64;        // [256]
    float* dinv  = red + 256;        // [64]

    const int bh = blockIdx.x / NLT;
    const int lt = blockIdx.x % NLT;
    const int t  = threadIdx.x;
    const int w  = t >> 5, lane = t & 31;
    const int gid = lane >> 2, t4 = lane & 3;

    // Q tile + g (fp32, via warp reduce during load)
    {
        const float4* Qg = (const float4*)(qin + ((size_t)bh*LTOT + lt*TL)*DD);
        #pragma unroll
        for (int r = 0; r < 8; r++) {
            int i = t + r*256;
            float4 v = Qg[i];
            float ss = v.x*v.x + v.y*v.y + v.z*v.z + v.w*v.w;
            ss += __shfl_xor_sync(0xffffffffu, ss, 16);
            ss += __shfl_xor_sync(0xffffffffu, ss, 8);
            ss += __shfl_xor_sync(0xffffffffu, ss, 4);
            ss += __shfl_xor_sync(0xffffffffu, ss, 2);
            ss += __shfl_xor_sync(0xffffffffu, ss, 1);
            if (lane == 0) g_s[r*8 + w] = ss * INV2SQD;
            v.x = to_tf32(v.x); v.y = to_tf32(v.y); v.z = to_tf32(v.z); v.w = to_tf32(v.w);
            *(float4*)&q_s[(i>>5)*LDX + (i&31)*4] = v;
        }
    }

    const int lb = w & 3, mh = w >> 2;   // GEMM A: S[16l x 32m]
    const int db = w >> 2;               // GEMM B: out[16l x 64d], same l-block lb

    float oacc[8][4];
    #pragma unroll
    for (int nb = 0; nb < 8; nb++)
        #pragma unroll
        for (int i = 0; i < 4; i++) oacc[nb][i] = 0.f;
    float dpr = 0.f;
    const int dl = t & 63, dq = t >> 6;

    for (int mc = 0; mc < NMT; mc++) {
        __syncthreads();   // prev GEMM B reads of pc_s/phi_s complete; q_s stores visible
        {
            const float4* Pg = (const float4*)(proj + (size_t)(mc*TM)*DD);
            #pragma unroll
            for (int r = 0; r < 8; r++) {
                int i = t + r*256;
                float4 v = Pg[i];
                v.x = to_tf32(v.x); v.y = to_tf32(v.y); v.z = to_tf32(v.z); v.w = to_tf32(v.w);
                *(float4*)&pc_s[(i>>5)*LDX + (i&31)*4] = v;
            }
        }
        __syncthreads();

        // GEMM A: S = Q @ P_chunk^T
        float c[4][4];
        #pragma unroll
        for (int nb = 0; nb < 4; nb++)
            #pragma unroll
            for (int i = 0; i < 4; i++) c[nb][i] = 0.f;
        #pragma unroll
        for (int kk = 0; kk < DD; kk += 8) {
            uint32_t a[4], b[2];
            const float* A0 = q_s + (lb*16 + gid)*LDX + kk + t4;
            a[0] = __float_as_uint(A0[0]);
            a[1] = __float_as_uint(A0[8*LDX]);
            a[2] = __float_as_uint(A0[4]);
            a[3] = __float_as_uint(A0[8*LDX + 4]);
            #pragma unroll
            for (int nb = 0; nb < 4; nb++) {
                const float* B0 = pc_s + (mh*32 + nb*8 + gid)*LDX + kk + t4;
                b[0] = __float_as_uint(B0[0]);
                b[1] = __float_as_uint(B0[4]);
                mma8(c[nb], a, b);
            }
        }
        __syncthreads();   // pc_s reads done

        // exp -> phi_s[l][m] (tf32); reload pc_s with ctx chunk; ksum chunk
        #pragma unroll
        for (int nb = 0; nb < 4; nb++) {
            int m0 = mh*32 + nb*8 + 2*t4;
            #pragma unroll
            for (int i = 0; i < 4; i++) {
                int l = lb*16 + gid + ((i >> 1) << 3);
                float ph = __expf(fmaf(c[nb][i], INV_SSD, CADD - g_s[l]));
                phi_s[l*PT + m0 + (i & 1)] = to_tf32(ph);
            }
        }
        {
            const float4* Cg = (const float4*)(g_ctx + ((size_t)bh*MM + mc*TM)*DD);
            #pragma unroll
            for (int r = 0; r < 8; r++) {
                int i = t + r*256;
                float4 v = Cg[i];
                v.x = to_tf32(v.x); v.y = to_tf32(v.y); v.z = to_tf32(v.z); v.w = to_tf32(v.w);
                *(float4*)&pc_s[(i>>5)*LDX + (i&31)*4] = v;
            }
        }
        if (t < 64) ks_s[t] = g_ksum[bh*MM + mc*TM + t];
        __syncthreads();

        // GEMM B: out += phi_s(16l x 64m) @ ctx(64m x 64d-half)
        #pragma unroll
        for (int kk = 0; kk < TM; kk += 8) {
            uint32_t a[4];
            const float* A0 = phi_s + (lb*16 + gid)*PT + kk + t4;
            a[0] = __float_as_uint(A0[0]);
            a[1] = __float_as_uint(A0[8*PT]);
            a[2] = __float_as_uint(A0[4]);
            a[3] = __float_as_uint(A0[8*PT + 4]);
            #pragma unroll
            for (int nb = 0; nb < 8; nb++) {
                uint32_t b[2];
                const float* B0 = pc_s + (kk + t4)*LDX + db*64 + nb*8 + gid;
                b[0] = __float_as_uint(B0[0]);
                b[1] = __float_as_uint(B0[4*LDX]);
                mma8(oacc[nb], a, b);
            }
        }
        // denominator partial: l = dl, m-range = dq*16..
        #pragma unroll
        for (int m0 = 0; m0 < 16; m0++)
            dpr += phi_s[dl*PT + dq*16 + m0] * ks_s[dq*16 + m0];
    }

    red[dq*64 + dl] = dpr;
    __syncthreads();
    if (t < 64)
        dinv[t] = 1.0f / (red[t] + red[64 + t] + red[128 + t] + red[192 + t]);
    __syncthreads();

    float* og = out + ((size_t)bh*LTOT + lt*TL)*DD;
    #pragma unroll
    for (int nb = 0; nb < 8; nb++) {
        int l0 = lb*16 + gid;
        int d  = db*64 + nb*8 + 2*t4;
        float i0 = dinv[l0], i1 = dinv[l0 + 8];
        *(float2*)&og[l0*DD + d]       = make_float2(oacc[nb][0]*i0, oacc[nb][1]*i0);
        *(float2*)&og[(l0 + 8)*DD + d] = make_float2(oacc[nb][2]*i1, oacc[nb][3]*i1);
    }
}

extern "C" void kernel_launch(void* const* d_in, const int* in_sizes, int n_in,
                              void* d_out, int out_size) {
    const float* q    = (const float*)d_in[0];
    const float* k    = (const float*)d_in[1];
    const float* v    = (const float*)d_in[2];
    const float* proj = (const float*)d_in[3];
    float* out = (float*)d_out;

    size_t smem1 = (TL*LDX + TM*LDX + TM*PT + 64 + 256) * sizeof(float);
    size_t smem2 = (TL*LDX + TM*LDX + TL*PT + 64 + 64 + 256 + 64) * sizeof(float);
    cudaFuncSetAttribute(k1_ctx_kernel, cudaFuncAttributeMaxDynamicSharedMemorySize, (int)smem1);
    cudaFuncSetAttribute(k2_out_kernel, cudaFuncAttributeMaxDynamicSharedMemorySize, (int)smem2);

    k1_ctx_kernel<<<BH * NMT, 256, smem1>>>(k, v, proj);
    k2_out_kernel<<<BH * NLT, 256, smem2>>>(q, proj, out);
}

// round 6
// speedup vs baseline: 3.3685x; 1.0345x over previous
#include <cuda_runtime.h>
#include <cstdint>

#define BH   32
#define LTOT 4096
#define DD   128
#define MM   640
#define TL   64
#define TM   64
#define NMT  (MM/TM)    // 10
#define NLT  (LTOT/TL)  // 64
#define TL2  128
#define NLT2 (LTOT/TL2) // 32
#define LDX  140        // padded stride: 140 mod 32 == 12 -> conflict-free frag patterns
#define PT   68         // phi stride: 68 mod 32 == 4

#define INV_SSD  0.2973017787506803f
#define INV2SQD  0.04419417382415922f
#define CADD    -3.2306341575510305f

// scratch: context [BH, M, D] fp32 + phi_k column sums [BH, M]
__device__ float g_ctx[(size_t)BH * MM * DD];
__device__ float g_ksum[BH * MM];

__device__ __forceinline__ float to_tf32(float x) {
    uint32_t u;
    asm("cvt.rna.tf32.f32 %0, %1;" : "=r"(u) : "f"(x));
    return __uint_as_float(u);
}

__device__ __forceinline__ void mma8(float* c, const uint32_t* a, const uint32_t* b) {
    asm volatile(
        "mma.sync.aligned.m16n8k8.row.col.f32.tf32.tf32.f32 "
        "{%0,%1,%2,%3},{%4,%5,%6,%7},{%8,%9},{%0,%1,%2,%3};\n"
        : "+f"(c[0]), "+f"(c[1]), "+f"(c[2]), "+f"(c[3])
        : "r"(a[0]), "r"(a[1]), "r"(a[2]), "r"(a[3]), "r"(b[0]), "r"(b[1]));
}

// ---------------------------------------------------------------------------
// K1: per (bh, m-tile of 64): ctx[64,128] = phi_k^T @ V ; ksum via ones-column
// ---------------------------------------------------------------------------
__global__ __launch_bounds__(256, 2) void k1_ctx_kernel(
    const float* __restrict__ kin, const float* __restrict__ vin,
    const float* __restrict__ proj)
{
    extern __shared__ float sm[];
    float* kv_s = sm;               // [64][140]  K chunk, then V chunk (+ones col 128)
    float* p_s  = kv_s + TL*LDX;    // [64][140]  P tile (persistent)
    float* phiT = p_s  + TM*LDX;    // [64 m][68 l]
    float* g_s  = phiT + TM*PT;     // [64]

    const int bh = blockIdx.x / NMT;
    const int mt = blockIdx.x % NMT;
    const int t  = threadIdx.x;
    const int w  = t >> 5, lane = t & 31;
    const int gid = lane >> 2, t4 = lane & 3;

    // P tile (tf32)
    {
        const float4* Pg = (const float4*)(proj + (size_t)(mt*TM)*DD);
        #pragma unroll
        for (int r = 0; r < 8; r++) {
            int i = t + r*256;
            float4 v = Pg[i];
            v.x = to_tf32(v.x); v.y = to_tf32(v.y); v.z = to_tf32(v.z); v.w = to_tf32(v.w);
            *(float4*)&p_s[(i>>5)*LDX + (i&31)*4] = v;
        }
    }
    // ones column for ksum-via-MMA (cols 128..135; loads never touch >=128)
    if (t < TL) {
        *(float4*)&kv_s[t*LDX + 128] = make_float4(1.f, 0.f, 0.f, 0.f);
        *(float4*)&kv_s[t*LDX + 132] = make_float4(0.f, 0.f, 0.f, 0.f);
    }

    const float* kg = kin + (size_t)bh*LTOT*DD;
    const float* vg = vin + (size_t)bh*LTOT*DD;

    const int lb = w & 3, mh = w >> 2;   // GEMM A warp tile: S[16l x 32m]
    const int mb = w & 3, db = w >> 2;   // GEMM B warp tile: ctx[16m x 64d]

    float ctxacc[8][4];
    #pragma unroll
    for (int nb = 0; nb < 8; nb++)
        #pragma unroll
        for (int i = 0; i < 4; i++) ctxacc[nb][i] = 0.f;
    float ksacc[4] = {0.f, 0.f, 0.f, 0.f};

    for (int lc = 0; lc < NLT; lc++) {
        __syncthreads();   // prev GEMM B reads of kv_s/phiT complete
        {
            const float4* Kg = (const float4*)(kg + (size_t)lc*TL*DD);
            #pragma unroll
            for (int r = 0; r < 8; r++) {
                int i = t + r*256;
                float4 v = Kg[i];
                float ss = v.x*v.x + v.y*v.y + v.z*v.z + v.w*v.w;
                ss += __shfl_xor_sync(0xffffffffu, ss, 16);
                ss += __shfl_xor_sync(0xffffffffu, ss, 8);
                ss += __shfl_xor_sync(0xffffffffu, ss, 4);
                ss += __shfl_xor_sync(0xffffffffu, ss, 2);
                ss += __shfl_xor_sync(0xffffffffu, ss, 1);
                if (lane == 0) g_s[r*8 + w] = ss * INV2SQD;
                v.x = to_tf32(v.x); v.y = to_tf32(v.y); v.z = to_tf32(v.z); v.w = to_tf32(v.w);
                *(float4*)&kv_s[(i>>5)*LDX + (i&31)*4] = v;
            }
        }
        __syncthreads();

        // GEMM A: S = K_chunk @ P^T
        float c[4][4];
        #pragma unroll
        for (int nb = 0; nb < 4; nb++)
            #pragma unroll
            for (int i = 0; i < 4; i++) c[nb][i] = 0.f;
        #pragma unroll
        for (int kk = 0; kk < DD; kk += 8) {
            uint32_t a[4], b[2];
            const float* A0 = kv_s + (lb*16 + gid)*LDX + kk + t4;
            a[0] = __float_as_uint(A0[0]);
            a[1] = __float_as_uint(A0[8*LDX]);
            a[2] = __float_as_uint(A0[4]);
            a[3] = __float_as_uint(A0[8*LDX + 4]);
            #pragma unroll
            for (int nb = 0; nb < 4; nb++) {
                const float* B0 = p_s + (mh*32 + nb*8 + gid)*LDX + kk + t4;
                b[0] = __float_as_uint(B0[0]);
                b[1] = __float_as_uint(B0[4]);
                mma8(c[nb], a, b);
            }
        }
        __syncthreads();   // kv_s reads done; g_s visible

        // exp -> phiT[m][l] (tf32), then reload kv_s with V chunk
        #pragma unroll
        for (int nb = 0; nb < 4; nb++) {
            int m0 = mh*32 + nb*8 + 2*t4;
            #pragma unroll
            for (int i = 0; i < 4; i++) {
                int l = lb*16 + gid + ((i >> 1) << 3);
                float ph = __expf(fmaf(c[nb][i], INV_SSD, CADD - g_s[l]));
                phiT[(m0 + (i & 1))*PT + l] = to_tf32(ph);
            }
        }
        {
            const float4* Vg = (const float4*)(vg + (size_t)lc*TL*DD);
            #pragma unroll
            for (int r = 0; r < 8; r++) {
                int i = t + r*256;
                float4 v = Vg[i];
                v.x = to_tf32(v.x); v.y = to_tf32(v.y); v.z = to_tf32(v.z); v.w = to_tf32(v.w);
                *(float4*)&kv_s[(i>>5)*LDX + (i&31)*4] = v;
            }
        }
        __syncthreads();

        // GEMM B: ctx += phiT(16m x 64l) @ V(64l x 64d-half); db==1 also does ones col
        #pragma unroll
        for (int kk = 0; kk < TL; kk += 8) {
            uint32_t a[4];
            const float* A0 = phiT + (mb*16 + gid)*PT + kk + t4;
            a[0] = __float_as_uint(A0[0]);
            a[1] = __float_as_uint(A0[8*PT]);
            a[2] = __float_as_uint(A0[4]);
            a[3] = __float_as_uint(A0[8*PT + 4]);
            #pragma unroll
            for (int nb = 0; nb < 8; nb++) {
                uint32_t b[2];
                const float* B0 = kv_s + (kk + t4)*LDX + db*64 + nb*8 + gid;
                b[0] = __float_as_uint(B0[0]);
                b[1] = __float_as_uint(B0[4*LDX]);
                mma8(ctxacc[nb], a, b);
            }
            if (db == 1) {
                uint32_t b[2];
                const float* B0 = kv_s + (kk + t4)*LDX + 128 + gid;
                b[0] = __float_as_uint(B0[0]);
                b[1] = __float_as_uint(B0[4*LDX]);
                mma8(ksacc, a, b);
            }
        }
    }

    // write ctx tile
    float* cg = g_ctx + ((size_t)bh*MM + mt*TM)*DD;
    #pragma unroll
    for (int nb = 0; nb < 8; nb++) {
        int m0 = mb*16 + gid;
        int d  = db*64 + nb*8 + 2*t4;
        *(float2*)&cg[m0*DD + d]       = make_float2(ctxacc[nb][0], ctxacc[nb][1]);
        *(float2*)&cg[(m0 + 8)*DD + d] = make_float2(ctxacc[nb][2], ctxacc[nb][3]);
    }
    // ksum from accumulator: d=128 column -> t4==0 threads, c[0]/c[2]
    if (db == 1 && t4 == 0) {
        g_ksum[bh*MM + mt*TM + mb*16 + gid]     = ksacc[0];
        g_ksum[bh*MM + mt*TM + mb*16 + gid + 8] = ksacc[2];
    }
}

// ---------------------------------------------------------------------------
// K2: per (bh, l-tile of 128): out = (phi_q @ ctx) / (phi_q @ ksum)
//     denominator folded into GEMM B via ksum column at d=128.
// ---------------------------------------------------------------------------
__global__ __launch_bounds__(256, 1) void k2_out_kernel(
    const float* __restrict__ qin, const float* __restrict__ proj,
    float* __restrict__ out)
{
    extern __shared__ float sm[];
    float* q_s   = sm;                  // [128][140]  Q tile (persistent)
    float* pc_s  = q_s + TL2*LDX;       // [64][140]   P chunk, then ctx chunk (+ks col)
    float* phi_s = pc_s + TM*LDX;       // [128 l][68 m]
    float* g_s   = phi_s + TL2*PT;      // [128]
    float* dinv  = g_s + TL2;           // [128]

    const int bh = blockIdx.x / NLT2;
    const int lt = blockIdx.x % NLT2;
    const int t  = threadIdx.x;
    const int w  = t >> 5, lane = t & 31;
    const int gid = lane >> 2, t4 = lane & 3;

    // Q tile 128x128 + g (fp32 via warp reduce during load)
    {
        const float4* Qg = (const float4*)(qin + ((size_t)bh*LTOT + lt*TL2)*DD);
        #pragma unroll
        for (int r = 0; r < 16; r++) {
            int i = t + r*256;
            float4 v = Qg[i];
            float ss = v.x*v.x + v.y*v.y + v.z*v.z + v.w*v.w;
            ss += __shfl_xor_sync(0xffffffffu, ss, 16);
            ss += __shfl_xor_sync(0xffffffffu, ss, 8);
            ss += __shfl_xor_sync(0xffffffffu, ss, 4);
            ss += __shfl_xor_sync(0xffffffffu, ss, 2);
            ss += __shfl_xor_sync(0xffffffffu, ss, 1);
            if (lane == 0) g_s[r*8 + w] = ss * INV2SQD;
            v.x = to_tf32(v.x); v.y = to_tf32(v.y); v.z = to_tf32(v.z); v.w = to_tf32(v.w);
            *(float4*)&q_s[(i>>5)*LDX + (i&31)*4] = v;
        }
    }

    const int lb = w & 3;     // l-block of 32 (shared by both GEMMs)
    const int mh = w >> 2;    // GEMM A: m-half of 32
    const int db = w >> 2;    // GEMM B: d-half of 64

    float oacc[2][8][4];
    #pragma unroll
    for (int ia = 0; ia < 2; ia++)
        #pragma unroll
        for (int nb = 0; nb < 8; nb++)
            #pragma unroll
            for (int i = 0; i < 4; i++) oacc[ia][nb][i] = 0.f;
    float dks[2][4];
    #pragma unroll
    for (int ia = 0; ia < 2; ia++)
        #pragma unroll
        for (int i = 0; i < 4; i++) dks[ia][i] = 0.f;

    for (int mc = 0; mc < NMT; mc++) {
        __syncthreads();   // prev GEMM B reads done; Q/g stores visible
        {
            const float4* Pg = (const float4*)(proj + (size_t)(mc*TM)*DD);
            #pragma unroll
            for (int r = 0; r < 8; r++) {
                int i = t + r*256;
                float4 v = Pg[i];
                v.x = to_tf32(v.x); v.y = to_tf32(v.y); v.z = to_tf32(v.z); v.w = to_tf32(v.w);
                *(float4*)&pc_s[(i>>5)*LDX + (i&31)*4] = v;
            }
        }
        __syncthreads();

        // GEMM A: S[128l x 64m] = Q @ P_chunk^T ; warp tile 32l x 32m
        float c[2][4][4];
        #pragma unroll
        for (int ia = 0; ia < 2; ia++)
            #pragma unroll
            for (int nb = 0; nb < 4; nb++)
                #pragma unroll
                for (int i = 0; i < 4; i++) c[ia][nb][i] = 0.f;
        #pragma unroll
        for (int kk = 0; kk < DD; kk += 8) {
            uint32_t a[2][4], b[2];
            #pragma unroll
            for (int ia = 0; ia < 2; ia++) {
                const float* A0 = q_s + (lb*32 + ia*16 + gid)*LDX + kk + t4;
                a[ia][0] = __float_as_uint(A0[0]);
                a[ia][1] = __float_as_uint(A0[8*LDX]);
                a[ia][2] = __float_as_uint(A0[4]);
                a[ia][3] = __float_as_uint(A0[8*LDX + 4]);
            }
            #pragma unroll
            for (int nb = 0; nb < 4; nb++) {
                const float* B0 = pc_s + (mh*32 + nb*8 + gid)*LDX + kk + t4;
                b[0] = __float_as_uint(B0[0]);
                b[1] = __float_as_uint(B0[4]);
                mma8(c[0][nb], a[0], b);
                mma8(c[1][nb], a[1], b);
            }
        }
        __syncthreads();   // pc_s reads done

        // exp -> phi_s[l][m] (tf32); reload pc_s with ctx chunk + ksum column
        #pragma unroll
        for (int ia = 0; ia < 2; ia++)
            #pragma unroll
            for (int nb = 0; nb < 4; nb++) {
                int m0 = mh*32 + nb*8 + 2*t4;
                #pragma unroll
                for (int i = 0; i < 4; i++) {
                    int l = lb*32 + ia*16 + gid + ((i >> 1) << 3);
                    float ph = __expf(fmaf(c[ia][nb][i], INV_SSD, CADD - g_s[l]));
                    phi_s[l*PT + m0 + (i & 1)] = to_tf32(ph);
                }
            }
        {
            const float4* Cg = (const float4*)(g_ctx + ((size_t)bh*MM + mc*TM)*DD);
            #pragma unroll
            for (int r = 0; r < 8; r++) {
                int i = t + r*256;
                float4 v = Cg[i];
                v.x = to_tf32(v.x); v.y = to_tf32(v.y); v.z = to_tf32(v.z); v.w = to_tf32(v.w);
                *(float4*)&pc_s[(i>>5)*LDX + (i&31)*4] = v;
            }
        }
        if (t < TM) {
            float ks = to_tf32(g_ksum[bh*MM + mc*TM + t]);
            *(float4*)&pc_s[t*LDX + 128] = make_float4(ks, 0.f, 0.f, 0.f);
            *(float4*)&pc_s[t*LDX + 132] = make_float4(0.f, 0.f, 0.f, 0.f);
        }
        __syncthreads();

        // GEMM B: out[128l x 128d] += phi(128x64) @ ctx(64x128); warp 32l x 64d
        #pragma unroll
        for (int kk = 0; kk < TM; kk += 8) {
            uint32_t a[2][4];
            #pragma unroll
            for (int ia = 0; ia < 2; ia++) {
                const float* A0 = phi_s + (lb*32 + ia*16 + gid)*PT + kk + t4;
                a[ia][0] = __float_as_uint(A0[0]);
                a[ia][1] = __float_as_uint(A0[8*PT]);
                a[ia][2] = __float_as_uint(A0[4]);
                a[ia][3] = __float_as_uint(A0[8*PT + 4]);
            }
            #pragma unroll
            for (int nb = 0; nb < 8; nb++) {
                uint32_t b[2];
                const float* B0 = pc_s + (kk + t4)*LDX + db*64 + nb*8 + gid;
                b[0] = __float_as_uint(B0[0]);
                b[1] = __float_as_uint(B0[4*LDX]);
                mma8(oacc[0][nb], a[0], b);
                mma8(oacc[1][nb], a[1], b);
            }
            if (db == 1) {
                uint32_t b[2];
                const float* B0 = pc_s + (kk + t4)*LDX + 128 + gid;
                b[0] = __float_as_uint(B0[0]);
                b[1] = __float_as_uint(B0[4*LDX]);
                mma8(dks[0], a[0], b);
                mma8(dks[1], a[1], b);
            }
        }
    }

    // denominator (d=128 col): db==1, t4==0 threads hold D[l] in dks[ia][0]/[2]
    if (db == 1 && t4 == 0) {
        #pragma unroll
        for (int ia = 0; ia < 2; ia++) {
            int l = lb*32 + ia*16 + gid;
            dinv[l]     = 1.0f / dks[ia][0];
            dinv[l + 8] = 1.0f / dks[ia][2];
        }
    }
    __syncthreads();

    float* og = out + ((size_t)bh*LTOT + lt*TL2)*DD;
    #pragma unroll
    for (int ia = 0; ia < 2; ia++)
        #pragma unroll
        for (int nb = 0; nb < 8; nb++) {
            int l0 = lb*32 + ia*16 + gid;
            int d  = db*64 + nb*8 + 2*t4;
            float i0 = dinv[l0], i1 = dinv[l0 + 8];
            *(float2*)&og[l0*DD + d]       = make_float2(oacc[ia][nb][0]*i0, oacc[ia][nb][1]*i0);
            *(float2*)&og[(l0 + 8)*DD + d] = make_float2(oacc[ia][nb][2]*i1, oacc[ia][nb][3]*i1);
        }
}

extern "C" void kernel_launch(void* const* d_in, const int* in_sizes, int n_in,
                              void* d_out, int out_size) {
    const float* q    = (const float*)d_in[0];
    const float* k    = (const float*)d_in[1];
    const float* v    = (const float*)d_in[2];
    const float* proj = (const float*)d_in[3];
    float* out = (float*)d_out;

    size_t smem1 = (TL*LDX + TM*LDX + TM*PT + 64) * sizeof(float);            // ~89.3 KB
    size_t smem2 = (TL2*LDX + TM*LDX + TL2*PT + TL2 + TL2) * sizeof(float);   // ~143.4 KB
    cudaFuncSetAttribute(k1_ctx_kernel, cudaFuncAttributeMaxDynamicSharedMemorySize, (int)smem1);
    cudaFuncSetAttribute(k2_out_kernel, cudaFuncAttributeMaxDynamicSharedMemorySize, (int)smem2);

    k1_ctx_kernel<<<BH * NMT, 256, smem1>>>(k, v, proj);
    k2_out_kernel<<<BH * NLT2, 256, smem2>>>(q, proj, out);
}

// round 7
// speedup vs baseline: 3.4037x; 1.0104x over previous
#include <cuda_runtime.h>
#include <cstdint>

#define BH   32
#define LTOT 4096
#define DD   128
#define MM   640
#define TL   64
#define TM   64
#define NMT  (MM/TM)    // 10
#define NLT  (LTOT/TL)  // 64
#define TL2  128
#define NLT2 (LTOT/TL2) // 32
#define LDX  136        // 136 mod 32 == 8 -> LDS.64 frag loads bank-bijective
#define PT   72         // 72 mod 32 == 8

#define INV_SSD  0.2973017787506803f
#define INV2SQD  0.04419417382415922f
#define CADD    -3.2306341575510305f

__device__ float g_ctx[(size_t)BH * MM * DD];
__device__ float g_ksum[BH * MM];

__device__ __forceinline__ float to_tf32(float x) {
    uint32_t u;
    asm("cvt.rna.tf32.f32 %0, %1;" : "=r"(u) : "f"(x));
    return __uint_as_float(u);
}

// permuted column position for MMA k-pairing: pairs (k, k+4) adjacent
__device__ __forceinline__ int pcol(int k) {
    return (k & ~7) | ((k & 3) << 1) | ((k >> 2) & 1);
}

__device__ __forceinline__ void mma8(float* c, const uint32_t* a, const uint32_t* b) {
    asm volatile(
        "mma.sync.aligned.m16n8k8.row.col.f32.tf32.tf32.f32 "
        "{%0,%1,%2,%3},{%4,%5,%6,%7},{%8,%9},{%0,%1,%2,%3};\n"
        : "+f"(c[0]), "+f"(c[1]), "+f"(c[2]), "+f"(c[3])
        : "r"(a[0]), "r"(a[1]), "r"(a[2]), "r"(a[3]), "r"(b[0]), "r"(b[1]));
}

// load a row-major global tile into smem with permuted k columns (tf32)
// i = t + r*256; row=i>>5 (warp-uniform), c=i&31; writes STS.128 at col c*4
__device__ __forceinline__ void load_perm(float* dst, const float* src, int i) {
    int row = i >> 5, c = i & 31;
    const float* g = src + row*DD + (c >> 1)*8 + (c & 1)*2;
    float2 u = *(const float2*)g;
    float2 w = *(const float2*)(g + 4);
    float4 o;
    o.x = to_tf32(u.x); o.y = to_tf32(w.x); o.z = to_tf32(u.y); o.w = to_tf32(w.y);
    *(float4*)&dst[row*LDX + c*4] = o;
}

// same but also computes row sum-of-squares via warp reduce into g_s[row]
__device__ __forceinline__ void load_perm_g(float* dst, float* g_s, const float* src,
                                            int i, int lane) {
    int row = i >> 5, c = i & 31;
    const float* g = src + row*DD + (c >> 1)*8 + (c & 1)*2;
    float2 u = *(const float2*)g;
    float2 w = *(const float2*)(g + 4);
    float ss = u.x*u.x + u.y*u.y + w.x*w.x + w.y*w.y;
    ss += __shfl_xor_sync(0xffffffffu, ss, 16);
    ss += __shfl_xor_sync(0xffffffffu, ss, 8);
    ss += __shfl_xor_sync(0xffffffffu, ss, 4);
    ss += __shfl_xor_sync(0xffffffffu, ss, 2);
    ss += __shfl_xor_sync(0xffffffffu, ss, 1);
    if (lane == 0) g_s[row] = ss * INV2SQD;
    float4 o;
    o.x = to_tf32(u.x); o.y = to_tf32(w.x); o.z = to_tf32(u.y); o.w = to_tf32(w.y);
    *(float4*)&dst[row*LDX + c*4] = o;
}

// plain tile load (V / ctx): k runs along rows for their MMA use
__device__ __forceinline__ void load_plain(float* dst, const float4* src, int i) {
    float4 v = src[i];
    v.x = to_tf32(v.x); v.y = to_tf32(v.y); v.z = to_tf32(v.z); v.w = to_tf32(v.w);
    *(float4*)&dst[(i >> 5)*LDX + (i & 31)*4] = v;
}

// paired a-fragment: rows base, base+8; k-pair at permuted kk+2*t4
__device__ __forceinline__ void lda(uint32_t* a, const float* A0, int rstride) {
    float2 x0 = *(const float2*)A0;
    float2 x1 = *(const float2*)(A0 + 8*rstride);
    a[0] = __float_as_uint(x0.x); a[1] = __float_as_uint(x1.x);
    a[2] = __float_as_uint(x0.y); a[3] = __float_as_uint(x1.y);
}

// ---------------------------------------------------------------------------
// K1: per (bh, m-tile of 64): ctx[64,128] = phi_k^T @ V ; ksum via ones-column
// ---------------------------------------------------------------------------
__global__ __launch_bounds__(256, 2) void k1_ctx_kernel(
    const float* __restrict__ kin, const float* __restrict__ vin,
    const float* __restrict__ proj)
{
    extern __shared__ float sm[];
    float* kv_s = sm;               // [64][136]  K (perm) / V (plain) + ones col 128
    float* p_s  = kv_s + TL*LDX;    // [64][136]  P tile (perm, persistent)
    float* phiT = p_s  + TM*LDX;    // [64 m][72] phi^T, l permuted
    float* g_s  = phiT + TM*PT;     // [64]

    const int bh = blockIdx.x / NMT;
    const int mt = blockIdx.x % NMT;
    const int t  = threadIdx.x;
    const int w  = t >> 5, lane = t & 31;
    const int gid = lane >> 2, t4 = lane & 3;

    {
        const float* Pg = proj + (size_t)(mt*TM)*DD;
        #pragma unroll
        for (int r = 0; r < 8; r++) load_perm(p_s, Pg, t + r*256);
    }
    if (t < TL) {
        *(float4*)&kv_s[t*LDX + 128] = make_float4(1.f, 0.f, 0.f, 0.f);
        *(float4*)&kv_s[t*LDX + 132] = make_float4(0.f, 0.f, 0.f, 0.f);
    }

    const float* kg = kin + (size_t)bh*LTOT*DD;
    const float* vg = vin + (size_t)bh*LTOT*DD;

    const int lb = w & 3, mh = w >> 2;   // GEMM A warp tile: S[16l x 32m]
    const int mb = w & 3, db = w >> 2;   // GEMM B warp tile: ctx[16m x 64d]

    float ctxacc[8][4];
    #pragma unroll
    for (int nb = 0; nb < 8; nb++)
        #pragma unroll
        for (int i = 0; i < 4; i++) ctxacc[nb][i] = 0.f;
    float ksacc[4] = {0.f, 0.f, 0.f, 0.f};

    for (int lc = 0; lc < NLT; lc++) {
        __syncthreads();
        {
            const float* Kg = kg + (size_t)lc*TL*DD;
            #pragma unroll
            for (int r = 0; r < 8; r++) load_perm_g(kv_s, g_s, Kg, t + r*256, lane);
        }
        __syncthreads();

        // GEMM A: S = K_chunk @ P^T
        float c[4][4];
        #pragma unroll
        for (int nb = 0; nb < 4; nb++)
            #pragma unroll
            for (int i = 0; i < 4; i++) c[nb][i] = 0.f;
        #pragma unroll
        for (int kk = 0; kk < DD; kk += 8) {
            uint32_t a[4], b[2];
            lda(a, kv_s + (lb*16 + gid)*LDX + kk + 2*t4, LDX);
            #pragma unroll
            for (int nb = 0; nb < 4; nb++) {
                float2 y = *(const float2*)(p_s + (mh*32 + nb*8 + gid)*LDX + kk + 2*t4);
                b[0] = __float_as_uint(y.x); b[1] = __float_as_uint(y.y);
                mma8(c[nb], a, b);
            }
        }
        __syncthreads();

        // exp -> phiT[m][p(l)] (tf32), then reload kv_s with V chunk (plain)
        #pragma unroll
        for (int nb = 0; nb < 4; nb++) {
            int m0 = mh*32 + nb*8 + 2*t4;
            #pragma unroll
            for (int i = 0; i < 4; i++) {
                int l = lb*16 + gid + ((i >> 1) << 3);
                float ph = __expf(fmaf(c[nb][i], INV_SSD, CADD - g_s[l]));
                phiT[(m0 + (i & 1))*PT + pcol(l)] = to_tf32(ph);
            }
        }
        {
            const float4* Vg = (const float4*)(vg + (size_t)lc*TL*DD);
            #pragma unroll
            for (int r = 0; r < 8; r++) load_plain(kv_s, Vg, t + r*256);
        }
        __syncthreads();

        // GEMM B: ctx += phiT(16m x 64l) @ V(64l x 64d-half); db==1 adds ones col
        #pragma unroll
        for (int kk = 0; kk < TL; kk += 8) {
            uint32_t a[4];
            lda(a, phiT + (mb*16 + gid)*PT + kk + 2*t4, PT);
            #pragma unroll
            for (int nb = 0; nb < 8; nb++) {
                uint32_t b[2];
                const float* B0 = kv_s + (kk + t4)*LDX + db*64 + nb*8 + gid;
                b[0] = __float_as_uint(B0[0]);
                b[1] = __float_as_uint(B0[4*LDX]);
                mma8(ctxacc[nb], a, b);
            }
            if (db == 1) {
                uint32_t b[2];
                const float* B0 = kv_s + (kk + t4)*LDX + 128 + gid;
                b[0] = __float_as_uint(B0[0]);
                b[1] = __float_as_uint(B0[4*LDX]);
                mma8(ksacc, a, b);
            }
        }
    }

    float* cg = g_ctx + ((size_t)bh*MM + mt*TM)*DD;
    #pragma unroll
    for (int nb = 0; nb < 8; nb++) {
        int m0 = mb*16 + gid;
        int d  = db*64 + nb*8 + 2*t4;
        *(float2*)&cg[m0*DD + d]       = make_float2(ctxacc[nb][0], ctxacc[nb][1]);
        *(float2*)&cg[(m0 + 8)*DD + d] = make_float2(ctxacc[nb][2], ctxacc[nb][3]);
    }
    if (db == 1 && t4 == 0) {
        g_ksum[bh*MM + mt*TM + mb*16 + gid]     = ksacc[0];
        g_ksum[bh*MM + mt*TM + mb*16 + gid + 8] = ksacc[2];
    }
}

// ---------------------------------------------------------------------------
// K2: per (bh, l-tile of 128): out = (phi_q @ ctx) / (phi_q @ ksum)
// ---------------------------------------------------------------------------
__global__ __launch_bounds__(256, 1) void k2_out_kernel(
    const float* __restrict__ qin, const float* __restrict__ proj,
    float* __restrict__ out)
{
    extern __shared__ float sm[];
    float* q_s   = sm;                  // [128][136]  Q (perm, persistent)
    float* pc_s  = q_s + TL2*LDX;       // [64][136]   P (perm) / ctx (plain) + ks col
    float* phi_s = pc_s + TM*LDX;       // [128 l][72] phi, m permuted
    float* g_s   = phi_s + TL2*PT;      // [128]
    float* dinv  = g_s + TL2;           // [128]

    const int bh = blockIdx.x / NLT2;
    const int lt = blockIdx.x % NLT2;
    const int t  = threadIdx.x;
    const int w  = t >> 5, lane = t & 31;
    const int gid = lane >> 2, t4 = lane & 3;

    {
        const float* Qg = qin + ((size_t)bh*LTOT + lt*TL2)*DD;
        #pragma unroll
        for (int r = 0; r < 16; r++) load_perm_g(q_s, g_s, Qg, t + r*256, lane);
    }

    const int lb = w & 3;     // l-block of 32 (both GEMMs)
    const int mh = w >> 2;    // GEMM A: m-half of 32
    const int db = w >> 2;    // GEMM B: d-half of 64

    float oacc[2][8][4];
    #pragma unroll
    for (int ia = 0; ia < 2; ia++)
        #pragma unroll
        for (int nb = 0; nb < 8; nb++)
            #pragma unroll
            for (int i = 0; i < 4; i++) oacc[ia][nb][i] = 0.f;
    float dks[2][4];
    #pragma unroll
    for (int ia = 0; ia < 2; ia++)
        #pragma unroll
        for (int i = 0; i < 4; i++) dks[ia][i] = 0.f;

    for (int mc = 0; mc < NMT; mc++) {
        __syncthreads();
        {
            const float* Pg = proj + (size_t)(mc*TM)*DD;
            #pragma unroll
            for (int r = 0; r < 8; r++) load_perm(pc_s, Pg, t + r*256);
        }
        __syncthreads();

        // GEMM A: S[128l x 64m] = Q @ P_chunk^T ; warp tile 32l x 32m
        float c[2][4][4];
        #pragma unroll
        for (int ia = 0; ia < 2; ia++)
            #pragma unroll
            for (int nb = 0; nb < 4; nb++)
                #pragma unroll
                for (int i = 0; i < 4; i++) c[ia][nb][i] = 0.f;
        #pragma unroll
        for (int kk = 0; kk < DD; kk += 8) {
            uint32_t a[2][4], b[2];
            #pragma unroll
            for (int ia = 0; ia < 2; ia++)
                lda(a[ia], q_s + (lb*32 + ia*16 + gid)*LDX + kk + 2*t4, LDX);
            #pragma unroll
            for (int nb = 0; nb < 4; nb++) {
                float2 y = *(const float2*)(pc_s + (mh*32 + nb*8 + gid)*LDX + kk + 2*t4);
                b[0] = __float_as_uint(y.x); b[1] = __float_as_uint(y.y);
                mma8(c[0][nb], a[0], b);
                mma8(c[1][nb], a[1], b);
            }
        }
        __syncthreads();

        // exp -> phi_s[l][p(m)] (tf32); reload pc_s with ctx (plain) + ks col
        #pragma unroll
        for (int ia = 0; ia < 2; ia++)
            #pragma unroll
            for (int nb = 0; nb < 4; nb++) {
                int m0 = mh*32 + nb*8 + 2*t4;
                #pragma unroll
                for (int i = 0; i < 4; i++) {
                    int l = lb*32 + ia*16 + gid + ((i >> 1) << 3);
                    float ph = __expf(fmaf(c[ia][nb][i], INV_SSD, CADD - g_s[l]));
                    phi_s[l*PT + pcol(m0 + (i & 1))] = to_tf32(ph);
                }
            }
        {
            const float4* Cg = (const float4*)(g_ctx + ((size_t)bh*MM + mc*TM)*DD);
            #pragma unroll
            for (int r = 0; r < 8; r++) load_plain(pc_s, Cg, t + r*256);
        }
        if (t < TM) {
            float ks = to_tf32(g_ksum[bh*MM + mc*TM + t]);
            *(float4*)&pc_s[t*LDX + 128] = make_float4(ks, 0.f, 0.f, 0.f);
            *(float4*)&pc_s[t*LDX + 132] = make_float4(0.f, 0.f, 0.f, 0.f);
        }
        __syncthreads();

        // GEMM B: out += phi(128x64) @ ctx(64x128); warp 32l x 64d; db==1 adds ks col
        #pragma unroll
        for (int kk = 0; kk < TM; kk += 8) {
            uint32_t a[2][4];
            #pragma unroll
            for (int ia = 0; ia < 2; ia++)
                lda(a[ia], phi_s + (lb*32 + ia*16 + gid)*PT + kk + 2*t4, PT);
            #pragma unroll
            for (int nb = 0; nb < 8; nb++) {
                uint32_t b[2];
                const float* B0 = pc_s + (kk + t4)*LDX + db*64 + nb*8 + gid;
                b[0] = __float_as_uint(B0[0]);
                b[1] = __float_as_uint(B0[4*LDX]);
                mma8(oacc[0][nb], a[0], b);
                mma8(oacc[1][nb], a[1], b);
            }
            if (db == 1) {
                uint32_t b[2];
                const float* B0 = pc_s + (kk + t4)*LDX + 128 + gid;
                b[0] = __float_as_uint(B0[0]);
                b[1] = __float_as_uint(B0[4*LDX]);
                mma8(dks[0], a[0], b);
                mma8(dks[1], a[1], b);
            }
        }
    }

    if (db == 1 && t4 == 0) {
        #pragma unroll
        for (int ia = 0; ia < 2; ia++) {
            int l = lb*32 + ia*16 + gid;
            dinv[l]     = 1.0f / dks[ia][0];
            dinv[l + 8] = 1.0f / dks[ia][2];
        }
    }
    __syncthreads();

    float* og = out + ((size_t)bh*LTOT + lt*TL2)*DD;
    #pragma unroll
    for (int ia = 0; ia < 2; ia++)
        #pragma unroll
        for (int nb = 0; nb < 8; nb++) {
            int l0 = lb*32 + ia*16 + gid;
            int d  = db*64 + nb*8 + 2*t4;
            float i0 = dinv[l0], i1 = dinv[l0 + 8];
            *(float2*)&og[l0*DD + d]       = make_float2(oacc[ia][nb][0]*i0, oacc[ia][nb][1]*i0);
            *(float2*)&og[(l0 + 8)*DD + d] = make_float2(oacc[ia][nb][2]*i1, oacc[ia][nb][3]*i1);
        }
}

extern "C" void kernel_launch(void* const* d_in, const int* in_sizes, int n_in,
                              void* d_out, int out_size) {
    const float* q    = (const float*)d_in[0];
    const float* k    = (const float*)d_in[1];
    const float* v    = (const float*)d_in[2];
    const float* proj = (const float*)d_in[3];
    float* out = (float*)d_out;

    size_t smem1 = (TL*LDX + TM*LDX + TM*PT + 64) * sizeof(float);            // ~86.3 KB
    size_t smem2 = (TL2*LDX + TM*LDX + TL2*PT + TL2 + TL2) * sizeof(float);   // ~139 KB
    cudaFuncSetAttribute(k1_ctx_kernel, cudaFuncAttributeMaxDynamicSharedMemorySize, (int)smem1);
    cudaFuncSetAttribute(k2_out_kernel, cudaFuncAttributeMaxDynamicSharedMemorySize, (int)smem2);

    k1_ctx_kernel<<<BH * NMT, 256, smem1>>>(k, v, proj);
    k2_out_kernel<<<BH * NLT2, 256, smem2>>>(q, proj, out);
}

// round 8
// speedup vs baseline: 4.3369x; 1.2742x over previous
#include <cuda_runtime.h>
#include <cstdint>

#define BH   32
#define LTOT 4096
#define DD   128
#define MM   640
#define TL   64
#define TM   64
#define NMT  (MM/TM)    // 10
#define NLT  (LTOT/TL)  // 64
#define NSPL 8          // k1 L-split
#define CHK  (NLT/NSPL) // 8 chunks per k1 block
#define TL2  128
#define NLT2 (LTOT/TL2) // 32
#define LDX1 136        // k1 strides (permuted layout)
#define PT1  72
#define LDX2 140        // k2 strides (R5 plain layout)
#define PT2  68

#define N4CTX (BH*MM*DD/4)  // 655360
#define N4KS  (BH*MM/4)     // 5120

#define INV_SSD  0.2973017787506803f
#define INV2SQD  0.04419417382415922f
#define CADD    -3.2306341575510305f

__device__ float g_ctx[(size_t)BH * MM * DD];
__device__ float g_ksum[BH * MM];
__device__ float g_ctx_part[NSPL][(size_t)BH * MM * DD];   // 84 MB
__device__ float g_ksum_part[NSPL][BH * MM];

__device__ __forceinline__ float to_tf32(float x) {
    uint32_t u;
    asm("cvt.rna.tf32.f32 %0, %1;" : "=r"(u) : "f"(x));
    return __uint_as_float(u);
}

__device__ __forceinline__ int pcol(int k) {
    return (k & ~7) | ((k & 3) << 1) | ((k >> 2) & 1);
}

__device__ __forceinline__ void mma8(float* c, const uint32_t* a, const uint32_t* b) {
    asm volatile(
        "mma.sync.aligned.m16n8k8.row.col.f32.tf32.tf32.f32 "
        "{%0,%1,%2,%3},{%4,%5,%6,%7},{%8,%9},{%0,%1,%2,%3};\n"
        : "+f"(c[0]), "+f"(c[1]), "+f"(c[2]), "+f"(c[3])
        : "r"(a[0]), "r"(a[1]), "r"(a[2]), "r"(a[3]), "r"(b[0]), "r"(b[1]));
}

// ===================== K1 helpers (permuted layout, stride LDX1) ============
__device__ __forceinline__ void load_perm(float* dst, const float* src, int i) {
    int row = i >> 5, c = i & 31;
    const float* g = src + row*DD + (c >> 1)*8 + (c & 1)*2;
    float2 u = *(const float2*)g;
    float2 w = *(const float2*)(g + 4);
    float4 o;
    o.x = to_tf32(u.x); o.y = to_tf32(w.x); o.z = to_tf32(u.y); o.w = to_tf32(w.y);
    *(float4*)&dst[row*LDX1 + c*4] = o;
}

__device__ __forceinline__ void load_perm_g(float* dst, float* g_s, const float* src,
                                            int i, int lane) {
    int row = i >> 5, c = i & 31;
    const float* g = src + row*DD + (c >> 1)*8 + (c & 1)*2;
    float2 u = *(const float2*)g;
    float2 w = *(const float2*)(g + 4);
    float ss = u.x*u.x + u.y*u.y + w.x*w.x + w.y*w.y;
    ss += __shfl_xor_sync(0xffffffffu, ss, 16);
    ss += __shfl_xor_sync(0xffffffffu, ss, 8);
    ss += __shfl_xor_sync(0xffffffffu, ss, 4);
    ss += __shfl_xor_sync(0xffffffffu, ss, 2);
    ss += __shfl_xor_sync(0xffffffffu, ss, 1);
    if (lane == 0) g_s[row] = ss * INV2SQD;
    float4 o;
    o.x = to_tf32(u.x); o.y = to_tf32(w.x); o.z = to_tf32(u.y); o.w = to_tf32(w.y);
    *(float4*)&dst[row*LDX1 + c*4] = o;
}

__device__ __forceinline__ void load_plain1(float* dst, const float4* src, int i) {
    float4 v = src[i];
    v.x = to_tf32(v.x); v.y = to_tf32(v.y); v.z = to_tf32(v.z); v.w = to_tf32(v.w);
    *(float4*)&dst[(i >> 5)*LDX1 + (i & 31)*4] = v;
}

__device__ __forceinline__ void lda64(uint32_t* a, const float* A0, int rstride) {
    float2 x0 = *(const float2*)A0;
    float2 x1 = *(const float2*)(A0 + 8*rstride);
    a[0] = __float_as_uint(x0.x); a[1] = __float_as_uint(x1.x);
    a[2] = __float_as_uint(x0.y); a[3] = __float_as_uint(x1.y);
}

// ---------------------------------------------------------------------------
// K1: per (bh, m-tile, l-split): partial ctx over 8 chunks; ksum via ones col
// ---------------------------------------------------------------------------
__global__ __launch_bounds__(256, 2) void k1_ctx_kernel(
    const float* __restrict__ kin, const float* __restrict__ vin,
    const float* __restrict__ proj)
{
    extern __shared__ float sm[];
    float* kv_s = sm;                // [64][136]
    float* p_s  = kv_s + TL*LDX1;    // [64][136]
    float* phiT = p_s  + TM*LDX1;    // [64 m][72]
    float* g_s  = phiT + TM*PT1;     // [64]

    const int bx = blockIdx.x;
    const int bh = bx / (NMT*NSPL);
    const int rr = bx % (NMT*NSPL);
    const int mt = rr / NSPL;
    const int ls = rr % NSPL;
    const int t  = threadIdx.x;
    const int w  = t >> 5, lane = t & 31;
    const int gid = lane >> 2, t4 = lane & 3;

    {
        const float* Pg = proj + (size_t)(mt*TM)*DD;
        #pragma unroll
        for (int r = 0; r < 8; r++) load_perm(p_s, Pg, t + r*256);
    }
    if (t < TL) {
        *(float4*)&kv_s[t*LDX1 + 128] = make_float4(1.f, 0.f, 0.f, 0.f);
        *(float4*)&kv_s[t*LDX1 + 132] = make_float4(0.f, 0.f, 0.f, 0.f);
    }

    const float* kg = kin + (size_t)bh*LTOT*DD;
    const float* vg = vin + (size_t)bh*LTOT*DD;

    const int lb = w & 3, mh = w >> 2;
    const int mb = w & 3, db = w >> 2;

    float ctxacc[8][4];
    #pragma unroll
    for (int nb = 0; nb < 8; nb++)
        #pragma unroll
        for (int i = 0; i < 4; i++) ctxacc[nb][i] = 0.f;
    float ksacc[4] = {0.f, 0.f, 0.f, 0.f};

    for (int lc = ls*CHK; lc < ls*CHK + CHK; lc++) {
        __syncthreads();
        {
            const float* Kg = kg + (size_t)lc*TL*DD;
            #pragma unroll
            for (int r = 0; r < 8; r++) load_perm_g(kv_s, g_s, Kg, t + r*256, lane);
        }
        __syncthreads();

        float c[4][4];
        #pragma unroll
        for (int nb = 0; nb < 4; nb++)
            #pragma unroll
            for (int i = 0; i < 4; i++) c[nb][i] = 0.f;
        #pragma unroll
        for (int kk = 0; kk < DD; kk += 8) {
            uint32_t a[4], b[2];
            lda64(a, kv_s + (lb*16 + gid)*LDX1 + kk + 2*t4, LDX1);
            #pragma unroll
            for (int nb = 0; nb < 4; nb++) {
                float2 y = *(const float2*)(p_s + (mh*32 + nb*8 + gid)*LDX1 + kk + 2*t4);
                b[0] = __float_as_uint(y.x); b[1] = __float_as_uint(y.y);
                mma8(c[nb], a, b);
            }
        }
        __syncthreads();

        #pragma unroll
        for (int nb = 0; nb < 4; nb++) {
            int m0 = mh*32 + nb*8 + 2*t4;
            #pragma unroll
            for (int i = 0; i < 4; i++) {
                int l = lb*16 + gid + ((i >> 1) << 3);
                float ph = __expf(fmaf(c[nb][i], INV_SSD, CADD - g_s[l]));
                phiT[(m0 + (i & 1))*PT1 + pcol(l)] = to_tf32(ph);
            }
        }
        {
            const float4* Vg = (const float4*)(vg + (size_t)lc*TL*DD);
            #pragma unroll
            for (int r = 0; r < 8; r++) load_plain1(kv_s, Vg, t + r*256);
        }
        __syncthreads();

        #pragma unroll
        for (int kk = 0; kk < TL; kk += 8) {
            uint32_t a[4];
            lda64(a, phiT + (mb*16 + gid)*PT1 + kk + 2*t4, PT1);
            #pragma unroll
            for (int nb = 0; nb < 8; nb++) {
                uint32_t b[2];
                const float* B0 = kv_s + (kk + t4)*LDX1 + db*64 + nb*8 + gid;
                b[0] = __float_as_uint(B0[0]);
                b[1] = __float_as_uint(B0[4*LDX1]);
                mma8(ctxacc[nb], a, b);
            }
            if (db == 1) {
                uint32_t b[2];
                const float* B0 = kv_s + (kk + t4)*LDX1 + 128 + gid;
                b[0] = __float_as_uint(B0[0]);
                b[1] = __float_as_uint(B0[4*LDX1]);
                mma8(ksacc, a, b);
            }
        }
    }

    float* cg = g_ctx_part[ls] + ((size_t)bh*MM + mt*TM)*DD;
    #pragma unroll
    for (int nb = 0; nb < 8; nb++) {
        int m0 = mb*16 + gid;
        int d  = db*64 + nb*8 + 2*t4;
        *(float2*)&cg[m0*DD + d]       = make_float2(ctxacc[nb][0], ctxacc[nb][1]);
        *(float2*)&cg[(m0 + 8)*DD + d] = make_float2(ctxacc[nb][2], ctxacc[nb][3]);
    }
    if (db == 1 && t4 == 0) {
        g_ksum_part[ls][bh*MM + mt*TM + mb*16 + gid]     = ksacc[0];
        g_ksum_part[ls][bh*MM + mt*TM + mb*16 + gid + 8] = ksacc[2];
    }
}

// ---------------------------------------------------------------------------
// KRED: g_ctx = sum of 8 partials; g_ksum likewise
// ---------------------------------------------------------------------------
__global__ __launch_bounds__(256) void kred_kernel()
{
    int i = blockIdx.x*256 + threadIdx.x;
    if (i < N4CTX) {
        float4 s = ((const float4*)g_ctx_part[0])[i];
        #pragma unroll
        for (int p = 1; p < NSPL; p++) {
            float4 a = ((const float4*)g_ctx_part[p])[i];
            s.x += a.x; s.y += a.y; s.z += a.z; s.w += a.w;
        }
        ((float4*)g_ctx)[i] = s;
    } else {
        int j = i - N4CTX;   // < N4KS
        float4 s = ((const float4*)g_ksum_part[0])[j];
        #pragma unroll
        for (int p = 1; p < NSPL; p++) {
            float4 a = ((const float4*)g_ksum_part[p])[j];
            s.x += a.x; s.y += a.y; s.z += a.z; s.w += a.w;
        }
        ((float4*)g_ksum)[j] = s;
    }
}

// ===================== K2 (R5 plain layout + cp.async pipelining) ==========
__device__ __forceinline__ void cp_tile(uint32_t sbase, const float* g, int t) {
    #pragma unroll
    for (int r = 0; r < 8; r++) {
        int i = t + r*256;
        uint32_t saddr = sbase + (((i >> 5)*LDX2 + (i & 31)*4) << 2);
        asm volatile("cp.async.cg.shared.global [%0], [%1], 16;"
                     :: "r"(saddr), "l"(g + 4*i));
    }
}

__global__ __launch_bounds__(256, 1) void k2_out_kernel(
    const float* __restrict__ qin, const float* __restrict__ proj,
    float* __restrict__ out)
{
    extern __shared__ float sm[];
    float* q_s   = sm;                  // [128][140]  Q (RNA tf32, persistent)
    float* p_buf = q_s + TL2*LDX2;      // [64][140]   P chunk (cp.async)
    float* c_buf = p_buf + TM*LDX2;     // [64][140]   ctx chunk (cp.async) + ks col
    float* phi_s = c_buf + TM*LDX2;     // [128 l][68 m]
    float* g_s   = phi_s + TL2*PT2;     // [128]
    float* dinv  = g_s + TL2;           // [128]

    const int bh = blockIdx.x / NLT2;
    const int lt = blockIdx.x % NLT2;
    const int t  = threadIdx.x;
    const int w  = t >> 5, lane = t & 31;
    const int gid = lane >> 2, t4 = lane & 3;

    const uint32_t pb_u = (uint32_t)__cvta_generic_to_shared(p_buf);
    const uint32_t cb_u = (uint32_t)__cvta_generic_to_shared(c_buf);

    // prefetch P[0]
    cp_tile(pb_u, proj, t);
    asm volatile("cp.async.commit_group;");

    // Q tile 128x128 + g (fp32 via warp reduce during load)
    {
        const float4* Qg = (const float4*)(qin + ((size_t)bh*LTOT + lt*TL2)*DD);
        #pragma unroll
        for (int r = 0; r < 16; r++) {
            int i = t + r*256;
            float4 v = Qg[i];
            float ss = v.x*v.x + v.y*v.y + v.z*v.z + v.w*v.w;
            ss += __shfl_xor_sync(0xffffffffu, ss, 16);
            ss += __shfl_xor_sync(0xffffffffu, ss, 8);
            ss += __shfl_xor_sync(0xffffffffu, ss, 4);
            ss += __shfl_xor_sync(0xffffffffu, ss, 2);
            ss += __shfl_xor_sync(0xffffffffu, ss, 1);
            if (lane == 0) g_s[r*8 + w] = ss * INV2SQD;
            v.x = to_tf32(v.x); v.y = to_tf32(v.y); v.z = to_tf32(v.z); v.w = to_tf32(v.w);
            *(float4*)&q_s[(i>>5)*LDX2 + (i&31)*4] = v;
        }
    }

    const int lb = w & 3;     // l-block of 32
    const int mh = w >> 2;    // GEMM A: m-half
    const int db = w >> 2;    // GEMM B: d-half

    float oacc[2][8][4];
    #pragma unroll
    for (int ia = 0; ia < 2; ia++)
        #pragma unroll
        for (int nb = 0; nb < 8; nb++)
            #pragma unroll
            for (int i = 0; i < 4; i++) oacc[ia][nb][i] = 0.f;
    float dks[2][4];
    #pragma unroll
    for (int ia = 0; ia < 2; ia++)
        #pragma unroll
        for (int i = 0; i < 4; i++) dks[ia][i] = 0.f;

    for (int mc = 0; mc < NMT; mc++) {
        __syncthreads();   // prev GEMM B done -> c_buf free; q/g visible (first iter)
        cp_tile(cb_u, g_ctx + ((size_t)bh*MM + mc*TM)*DD, t);
        asm volatile("cp.async.commit_group;");        // group C[mc]
        asm volatile("cp.async.wait_group 1;");        // P[mc] arrived
        __syncthreads();                               // p_buf published

        // GEMM A: S[128l x 64m] = Q @ P_chunk^T
        float c[2][4][4];
        #pragma unroll
        for (int ia = 0; ia < 2; ia++)
            #pragma unroll
            for (int nb = 0; nb < 4; nb++)
                #pragma unroll
                for (int i = 0; i < 4; i++) c[ia][nb][i] = 0.f;
        #pragma unroll
        for (int kk = 0; kk < DD; kk += 8) {
            uint32_t a[2][4], b[2];
            #pragma unroll
            for (int ia = 0; ia < 2; ia++) {
                const float* A0 = q_s + (lb*32 + ia*16 + gid)*LDX2 + kk + t4;
                a[ia][0] = __float_as_uint(A0[0]);
                a[ia][1] = __float_as_uint(A0[8*LDX2]);
                a[ia][2] = __float_as_uint(A0[4]);
                a[ia][3] = __float_as_uint(A0[8*LDX2 + 4]);
            }
            #pragma unroll
            for (int nb = 0; nb < 4; nb++) {
                const float* B0 = p_buf + (mh*32 + nb*8 + gid)*LDX2 + kk + t4;
                b[0] = __float_as_uint(B0[0]);
                b[1] = __float_as_uint(B0[4]);
                mma8(c[0][nb], a[0], b);
                mma8(c[1][nb], a[1], b);
            }
        }
        __syncthreads();   // p_buf free (also phi free from prev iter)

        // prefetch P[mc+1] (empty commit on last iter keeps group counting uniform)
        if (mc + 1 < NMT) cp_tile(pb_u, proj + (size_t)((mc+1)*TM)*DD, t);
        asm volatile("cp.async.commit_group;");        // group P[mc+1]

        // exp -> phi_s[l][m] (RNA tf32)
        #pragma unroll
        for (int ia = 0; ia < 2; ia++)
            #pragma unroll
            for (int nb = 0; nb < 4; nb++) {
                int m0 = mh*32 + nb*8 + 2*t4;
                #pragma unroll
                for (int i = 0; i < 4; i++) {
                    int l = lb*32 + ia*16 + gid + ((i >> 1) << 3);
                    float ph = __expf(fmaf(c[ia][nb][i], INV_SSD, CADD - g_s[l]));
                    phi_s[l*PT2 + m0 + (i & 1)] = to_tf32(ph);
                }
            }
        if (t < TM) {
            float ks = to_tf32(g_ksum[bh*MM + mc*TM + t]);
            *(float4*)&c_buf[t*LDX2 + 128] = make_float4(ks, 0.f, 0.f, 0.f);
            *(float4*)&c_buf[t*LDX2 + 132] = make_float4(0.f, 0.f, 0.f, 0.f);
        }
        asm volatile("cp.async.wait_group 1;");        // C[mc] arrived
        __syncthreads();                               // c_buf + phi + ks published

        // GEMM B: out += phi(128x64) @ ctx(64x128); db==1 adds ks column
        #pragma unroll
        for (int kk = 0; kk < TM; kk += 8) {
            uint32_t a[2][4];
            #pragma unroll
            for (int ia = 0; ia < 2; ia++) {
                const float* A0 = phi_s + (lb*32 + ia*16 + gid)*PT2 + kk + t4;
                a[ia][0] = __float_as_uint(A0[0]);
                a[ia][1] = __float_as_uint(A0[8*PT2]);
                a[ia][2] = __float_as_uint(A0[4]);
                a[ia][3] = __float_as_uint(A0[8*PT2 + 4]);
            }
            #pragma unroll
            for (int nb = 0; nb < 8; nb++) {
                uint32_t b[2];
                const float* B0 = c_buf + (kk + t4)*LDX2 + db*64 + nb*8 + gid;
                b[0] = __float_as_uint(B0[0]);
                b[1] = __float_as_uint(B0[4*LDX2]);
                mma8(oacc[0][nb], a[0], b);
                mma8(oacc[1][nb], a[1], b);
            }
            if (db == 1) {
                uint32_t b[2];
                const float* B0 = c_buf + (kk + t4)*LDX2 + 128 + gid;
                b[0] = __float_as_uint(B0[0]);
                b[1] = __float_as_uint(B0[4*LDX2]);
                mma8(dks[0], a[0], b);
                mma8(dks[1], a[1], b);
            }
        }
    }

    if (db == 1 && t4 == 0) {
        #pragma unroll
        for (int ia = 0; ia < 2; ia++) {
            int l = lb*32 + ia*16 + gid;
            dinv[l]     = 1.0f / dks[ia][0];
            dinv[l + 8] = 1.0f / dks[ia][2];
        }
    }
    __syncthreads();

    float* og = out + ((size_t)bh*LTOT + lt*TL2)*DD;
    #pragma unroll
    for (int ia = 0; ia < 2; ia++)
        #pragma unroll
        for (int nb = 0; nb < 8; nb++) {
            int l0 = lb*32 + ia*16 + gid;
            int d  = db*64 + nb*8 + 2*t4;
            float i0 = dinv[l0], i1 = dinv[l0 + 8];
            *(float2*)&og[l0*DD + d]       = make_float2(oacc[ia][nb][0]*i0, oacc[ia][nb][1]*i0);
            *(float2*)&og[(l0 + 8)*DD + d] = make_float2(oacc[ia][nb][2]*i1, oacc[ia][nb][3]*i1);
        }
}

extern "C" void kernel_launch(void* const* d_in, const int* in_sizes, int n_in,
                              void* d_out, int out_size) {
    const float* q    = (const float*)d_in[0];
    const float* k    = (const float*)d_in[1];
    const float* v    = (const float*)d_in[2];
    const float* proj = (const float*)d_in[3];
    float* out = (float*)d_out;

    size_t smem1 = (TL*LDX1 + TM*LDX1 + TM*PT1 + 64) * sizeof(float);              // ~86.3 KB
    size_t smem2 = (TL2*LDX2 + 2*TM*LDX2 + TL2*PT2 + TL2 + TL2) * sizeof(float);   // ~179 KB
    cudaFuncSetAttribute(k1_ctx_kernel, cudaFuncAttributeMaxDynamicSharedMemorySize, (int)smem1);
    cudaFuncSetAttribute(k2_out_kernel, cudaFuncAttributeMaxDynamicSharedMemorySize, (int)smem2);

    k1_ctx_kernel<<<BH * NMT * NSPL, 256, smem1>>>(k, v, proj);
    kred_kernel<<<(N4CTX + N4KS) / 256, 256>>>();
    k2_out_kernel<<<BH * NLT2, 256, smem2>>>(q, proj, out);
}